// round 6
// baseline (speedup 1.0000x reference)
#include <cuda_runtime.h>
#include <float.h>

// ---------------------------------------------------------------------------
// Problem shape
// ---------------------------------------------------------------------------
#define M_Q   2048
#define N_P   32768
#define D_F   256
#define D2    512

#define NPART 16
#define PART  (N_P / NPART)      // 2048 candidates per partition (== one tile)
#define TP    (PART / 2)         // 1024 packed units
#define QPW   8                  // queries per warp
#define SUBP  128                // packed units per sub-block (256 candidates)
#define NSUB  (TP / SUBP)        // 8 sub-blocks

typedef unsigned long long ull;

// ---------------------------------------------------------------------------
// Device scratch
// ---------------------------------------------------------------------------
__device__ float2       g_nn_part[4][M_Q][NPART];  // (best d2', exact idx bits)
__device__ unsigned int g_xmax[D2];                // order-encoded channel max
__device__ float        g_h[D2];                   // fc1 out * w2
__device__ unsigned int g_tick;                    // fc last-block ticket

// ---------------------------------------------------------------------------
// Packed f32x2 helpers
// ---------------------------------------------------------------------------
__device__ __forceinline__ ull fma2(ull a, ull b, ull c) {
    ull d;
    asm("fma.rn.f32x2 %0, %1, %2, %3;" : "=l"(d) : "l"(a), "l"(b), "l"(c));
    return d;
}
__device__ __forceinline__ ull mul2(ull a, ull b) {
    ull d;
    asm("mul.rn.f32x2 %0, %1, %2;" : "=l"(d) : "l"(a), "l"(b));
    return d;
}
__device__ __forceinline__ void fma2u(ull a, ull b, ull c, float& lo, float& hi) {
    asm("{\n\t.reg .b64 t;\n\t"
        "fma.rn.f32x2 t, %2, %3, %4;\n\t"
        "mov.b64 {%0, %1}, t;\n\t}"
        : "=f"(lo), "=f"(hi) : "l"(a), "l"(b), "l"(c));
}
__device__ __forceinline__ ull pack2(float lo, float hi) {
    ull r;
    asm("mov.b64 %0, {%1, %2};" : "=l"(r) : "f"(lo), "f"(hi));
    return r;
}

// Order-preserving float<->uint for atomicMax over mixed-sign floats.
__device__ __forceinline__ unsigned int enc_f(float f) {
    unsigned int u = __float_as_uint(f);
    return (u & 0x80000000u) ? ~u : (u | 0x80000000u);
}
__device__ __forceinline__ float dec_f(unsigned int u) {
    return __uint_as_float((u & 0x80000000u) ? (u & 0x7FFFFFFFu) : ~u);
}

// ---------------------------------------------------------------------------
// Kernel 1: brute-force NN (min-only loop, sub-block tracking) + in-SMEM
// exact-index rescan. d2' = |p|^2 - 2 q.p (argmin-equivalent to |q-p|^2).
// Grid: 2048 blocks = 32 qblocks x 4 searches x 16 partitions. 256 thr.
// ---------------------------------------------------------------------------
__global__ __launch_bounds__(256, 3)
void nn_kernel(const float* __restrict__ co, const float* __restrict__ cm,
               const float* __restrict__ p0, const float* __restrict__ p1,
               const float* __restrict__ p2, const float* __restrict__ p3)
{
    const int bx     = blockIdx.x;
    const int part   = bx & 15;
    const int search = (bx >> 4) & 3;
    const int qblk   = bx >> 6;               // 0..31
    const int tid    = threadIdx.x;
    const int warp   = tid >> 5;
    const int lane   = tid & 31;

    if (bx < 2) g_xmax[bx * 256 + tid] = 0u;  // init for gather stage
    if (bx == 0 && tid == 0) g_tick = 0u;     // init fc ticket

    const float* __restrict__ q   = (search < 2) ? co : cm;
    const float* __restrict__ pos = (search == 0) ? p0 :
                                    (search == 1) ? p1 :
                                    (search == 2) ? p2 : p3;

    const int qbase = qblk * 64 + warp * QPW;

    ull   cx2[QPW], cy2[QPW], cz2[QPW];
    float best[QPW];
    int   bsub[QPW];
#pragma unroll
    for (int j = 0; j < QPW; j++) {
        const int qi = qbase + j;
        const float nx = -2.0f * q[qi * 3 + 0];
        const float ny = -2.0f * q[qi * 3 + 1];
        const float nz = -2.0f * q[qi * 3 + 2];
        cx2[j] = pack2(nx, nx);
        cy2[j] = pack2(ny, ny);
        cz2[j] = pack2(nz, nz);
        best[j] = FLT_MAX;
        bsub[j] = 0;
    }

    // interleaved tile: sxy[k] = (x2,y2), szw[k] = (z2,w2)  -> LDS.128 pairs
    __shared__ ulonglong2 sxy[TP], szw[TP];   // 32 KB

    const int pbase = part * PART;

    for (int u = tid; u < TP; u += 256) {
        const float2* pp = (const float2*)(pos + (size_t)(pbase + 2 * u) * 3);
        const float2 a = pp[0];            // x0 y0
        const float2 b = pp[1];            // z0 x1
        const float2 c = pp[2];            // y1 z1
        const ull x2 = pack2(a.x, b.y);
        const ull y2 = pack2(a.y, c.x);
        const ull z2 = pack2(b.x, c.y);
        ull w2 = mul2(z2, z2);
        w2 = fma2(y2, y2, w2);
        w2 = fma2(x2, x2, w2);
        sxy[u] = make_ulonglong2(x2, y2);
        szw[u] = make_ulonglong2(z2, w2);
    }
    __syncthreads();

#pragma unroll 1
    for (int s = 0; s < NSUB; s++) {
        float tmin[QPW];
#pragma unroll
        for (int j = 0; j < QPW; j++) tmin[j] = best[j];

#pragma unroll
        for (int kk = 0; kk < SUBP / 32; kk++) {       // 4 k-iters
            const int k = s * SUBP + kk * 32 + lane;
            const ulonglong2 va = sxy[k];
            const ulonglong2 vb = szw[k];
#pragma unroll
            for (int j = 0; j < QPW; j++) {
                ull t2 = fma2(va.x, cx2[j], vb.y);
                t2 = fma2(va.y, cy2[j], t2);
                float lo, hi;
                fma2u(vb.x, cz2[j], t2, lo, hi);
                tmin[j] = fminf(tmin[j], fminf(lo, hi));
            }
        }

        const int gb = s * SUBP;                       // packed-unit sub base
#pragma unroll
        for (int j = 0; j < QPW; j++) {
            if (tmin[j] < best[j]) { best[j] = tmin[j]; bsub[j] = gb; }
        }
    }

    // cross-lane lexicographic (best, bsub) reduce -> warp-uniform winners
#pragma unroll
    for (int off = 16; off; off >>= 1) {
#pragma unroll
        for (int j = 0; j < QPW; j++) {
            const float ob = __shfl_xor_sync(0xffffffffu, best[j], off);
            const int   og = __shfl_xor_sync(0xffffffffu, bsub[j], off);
            if (ob < best[j] || (ob == best[j] && og < bsub[j])) {
                best[j] = ob; bsub[j] = og;
            }
        }
    }

    // exact index rescan of the winning sub-block, from SMEM (resident)
#pragma unroll 1
    for (int j = 0; j < QPW; j++) {
        const float wb = best[j];
        const int   u0 = bsub[j];                      // packed-unit base
        int midx = 0x7fffffff;
#pragma unroll
        for (int kk = 0; kk < SUBP / 32; kk++) {
            const int k = u0 + kk * 32 + lane;
            const ulonglong2 va = sxy[k];
            const ulonglong2 vb = szw[k];
            ull t2 = fma2(va.x, cx2[j], vb.y);
            t2 = fma2(va.y, cy2[j], t2);
            float lo, hi;
            fma2u(vb.x, cz2[j], t2, lo, hi);
            const int i0 = pbase + 2 * k;
            if (lo == wb) midx = min(midx, i0);
            if (hi == wb) midx = min(midx, i0 + 1);
        }
#pragma unroll
        for (int off = 16; off; off >>= 1)
            midx = min(midx, __shfl_xor_sync(0xffffffffu, midx, off));

        if (lane == 0)
            g_nn_part[search][qbase + j][part] =
                make_float2(wb, __int_as_float(midx));
    }
}

// ---------------------------------------------------------------------------
// Kernel 2: resolve partitions (lex-min d2 then idx), gather feat rows,
// avg left/right, max-pool via deterministic atomicMax.
// Grid: 256 blocks = 2 sides x 128 chunks (16 rows). 256 thr.
// ---------------------------------------------------------------------------
__global__ __launch_bounds__(256)
void gather_kernel(const float* __restrict__ f0, const float* __restrict__ f1,
                   const float* __restrict__ f2, const float* __restrict__ f3)
{
    const int side  = blockIdx.x >> 7;     // 0 = orig, 1 = mut
    const int chunk = blockIdx.x & 127;
    const int m0    = chunk * 16;
    const int tid   = threadIdx.x;
    const int warp  = tid >> 5;
    const int lane  = tid & 31;

    __shared__ int sj[2][16];

    // 8 warps x 4 resolves = 32 (which,row) pairs
#pragma unroll
    for (int pr = warp * 4; pr < warp * 4 + 4; pr++) {
        const int which = pr >> 4;
        const int ml    = pr & 15;
        const int s     = side * 2 + which;

        float v = FLT_MAX;
        int   g = 0x7fffffff;
        if (lane < NPART) {
            const float2 p = g_nn_part[s][m0 + ml][lane];
            v = p.x; g = __float_as_int(p.y);
        }
#pragma unroll
        for (int off = 8; off; off >>= 1) {
            const float ov = __shfl_xor_sync(0xffffffffu, v, off);
            const int   og = __shfl_xor_sync(0xffffffffu, g, off);
            if (ov < v || (ov == v && og < g)) { v = ov; g = og; }
        }
        if (lane == 0) sj[which][ml] = g;
    }
    __syncthreads();

    const float* __restrict__ fa = side ? f2 : f0;
    const float* __restrict__ fb = side ? f3 : f1;
    const int c = tid;

    float mx = -FLT_MAX;
#pragma unroll
    for (int m = 0; m < 16; m++) {
        const float val = 0.5f * (fa[(size_t)sj[0][m] * D_F + c] +
                                  fb[(size_t)sj[1][m] * D_F + c]);
        mx = fmaxf(mx, val);
    }
    atomicMax(&g_xmax[side * 256 + c], enc_f(mx));
}

// ---------------------------------------------------------------------------
// Kernel 3: fc1 over 128 blocks (4 rows each, warp per row); last block
// finishes fc2 (threadfence-reduction pattern, deterministic order).
// ---------------------------------------------------------------------------
__global__ __launch_bounds__(128)
void fc_kernel(const float* __restrict__ w1, const float* __restrict__ b1,
               const float* __restrict__ w2, const float* __restrict__ b2,
               float* __restrict__ out)
{
    __shared__ float xs[D2];
    __shared__ bool  is_last;
    __shared__ float red[4];
    const int tid  = threadIdx.x;
    const int warp = tid >> 5;
    const int lane = tid & 31;

    for (int i = tid; i < D2; i += 128) xs[i] = dec_f(g_xmax[i]);
    __syncthreads();

    const int j = blockIdx.x * 4 + warp;
    const float4* __restrict__ wr4 = (const float4*)(w1 + (size_t)j * D2);
    const float4* __restrict__ xs4 = (const float4*)xs;

    float acc = 0.0f;
#pragma unroll
    for (int k = lane; k < D2 / 4; k += 32) {
        const float4 w = wr4[k];
        const float4 x = xs4[k];
        acc = fmaf(w.x, x.x, acc);
        acc = fmaf(w.y, x.y, acc);
        acc = fmaf(w.z, x.z, acc);
        acc = fmaf(w.w, x.w, acc);
    }
#pragma unroll
    for (int off = 16; off; off >>= 1)
        acc += __shfl_down_sync(0xffffffffu, acc, off);

    if (lane == 0)
        g_h[j] = fmaxf(acc + b1[j], 0.0f) * w2[j];

    // last-block fc2
    __threadfence();
    __syncthreads();
    if (tid == 0)
        is_last = (atomicAdd(&g_tick, 1u) == 127u);
    __syncthreads();

    if (is_last) {
        __threadfence();                    // acquire all g_h writes
        const float4 v = ((const float4*)g_h)[tid];     // 128 x float4 = 512
        float a2 = v.x + v.y + v.z + v.w;
#pragma unroll
        for (int off = 16; off; off >>= 1)
            a2 += __shfl_down_sync(0xffffffffu, a2, off);
        if (lane == 0) red[warp] = a2;
        __syncthreads();
        if (tid == 0)
            out[0] = red[0] + red[1] + red[2] + red[3] + b2[0];
    }
}

// ---------------------------------------------------------------------------
// Launch
// ---------------------------------------------------------------------------
extern "C" void kernel_launch(void* const* d_in, const int* in_sizes, int n_in,
                              void* d_out, int out_size)
{
    const float* co = (const float*)d_in[0];
    const float* cm = (const float*)d_in[1];
    const float* p0 = (const float*)d_in[2];
    const float* p1 = (const float*)d_in[3];
    const float* p2 = (const float*)d_in[4];
    const float* p3 = (const float*)d_in[5];
    const float* f0 = (const float*)d_in[6];
    const float* f1 = (const float*)d_in[7];
    const float* f2 = (const float*)d_in[8];
    const float* f3 = (const float*)d_in[9];
    const float* w1 = (const float*)d_in[10];
    const float* b1 = (const float*)d_in[11];
    const float* w2 = (const float*)d_in[12];
    const float* b2 = (const float*)d_in[13];
    float* out = (float*)d_out;

    nn_kernel<<<2048, 256>>>(co, cm, p0, p1, p2, p3);
    gather_kernel<<<256, 256>>>(f0, f1, f2, f3);
    fc_kernel<<<128, 128>>>(w1, b1, w2, b2, out);
}

// round 7
// speedup vs baseline: 1.6557x; 1.6557x over previous
#include <cuda_runtime.h>
#include <float.h>

// ---------------------------------------------------------------------------
// Problem shape
// ---------------------------------------------------------------------------
#define M_Q   2048
#define N_P   32768
#define D_F   256
#define D2    512

#define NPART 16
#define PART  (N_P / NPART)      // 2048 candidates per partition (== one tile)
#define TP    (PART / 2)         // 1024 packed units
#define QPW   8                  // queries per warp
#define SUBP  128                // packed units per sub-block (256 candidates)
#define NSUB  (TP / SUBP)        // 8 sub-blocks

typedef unsigned long long ull;

// ---------------------------------------------------------------------------
// Device scratch
// ---------------------------------------------------------------------------
__device__ float2       g_nn_part[4][M_Q][NPART];  // (best d2', sub-base bits)
__device__ unsigned int g_xmax[D2];                // order-encoded channel max
__device__ float        g_h[D2];                   // fc1 out * w2
__device__ unsigned int g_tick;                    // fc last-block ticket

// ---------------------------------------------------------------------------
// Packed f32x2 helpers
// ---------------------------------------------------------------------------
__device__ __forceinline__ ull fma2(ull a, ull b, ull c) {
    ull d;
    asm("fma.rn.f32x2 %0, %1, %2, %3;" : "=l"(d) : "l"(a), "l"(b), "l"(c));
    return d;
}
__device__ __forceinline__ ull mul2(ull a, ull b) {
    ull d;
    asm("mul.rn.f32x2 %0, %1, %2;" : "=l"(d) : "l"(a), "l"(b));
    return d;
}
__device__ __forceinline__ void fma2u(ull a, ull b, ull c, float& lo, float& hi) {
    asm("{\n\t.reg .b64 t;\n\t"
        "fma.rn.f32x2 t, %2, %3, %4;\n\t"
        "mov.b64 {%0, %1}, t;\n\t}"
        : "=f"(lo), "=f"(hi) : "l"(a), "l"(b), "l"(c));
}
__device__ __forceinline__ ull pack2(float lo, float hi) {
    ull r;
    asm("mov.b64 %0, {%1, %2};" : "=l"(r) : "f"(lo), "f"(hi));
    return r;
}

// Order-preserving float<->uint for atomicMax over mixed-sign floats.
__device__ __forceinline__ unsigned int enc_f(float f) {
    unsigned int u = __float_as_uint(f);
    return (u & 0x80000000u) ? ~u : (u | 0x80000000u);
}
__device__ __forceinline__ float dec_f(unsigned int u) {
    return __uint_as_float((u & 0x80000000u) ? (u & 0x7FFFFFFFu) : ~u);
}

// ---------------------------------------------------------------------------
// Kernel 1: brute-force NN, min-only loop + 256-cand sub-block tracking.
// d2' = |p|^2 - 2 q.p  (argmin-equivalent to |q-p|^2)
// Grid: 2048 blocks = 32 qblocks x 4 searches x 16 partitions. 256 thr.
// (R5-proven layout: 4 separate SoA arrays, LDS.64 accesses.)
// ---------------------------------------------------------------------------
__global__ __launch_bounds__(256, 3)
void nn_kernel(const float* __restrict__ co, const float* __restrict__ cm,
               const float* __restrict__ p0, const float* __restrict__ p1,
               const float* __restrict__ p2, const float* __restrict__ p3)
{
    const int bx     = blockIdx.x;
    const int part   = bx & 15;
    const int search = (bx >> 4) & 3;
    const int qblk   = bx >> 6;               // 0..31
    const int tid    = threadIdx.x;
    const int warp   = tid >> 5;
    const int lane   = tid & 31;

    if (bx < 2) g_xmax[bx * 256 + tid] = 0u;  // init for gather stage
    if (bx == 0 && tid == 0) g_tick = 0u;     // init fc ticket

    const float* __restrict__ q   = (search < 2) ? co : cm;
    const float* __restrict__ pos = (search == 0) ? p0 :
                                    (search == 1) ? p1 :
                                    (search == 2) ? p2 : p3;

    const int qbase = qblk * 64 + warp * QPW;

    ull   cx2[QPW], cy2[QPW], cz2[QPW];
    float best[QPW];
    int   bsub[QPW];
#pragma unroll
    for (int j = 0; j < QPW; j++) {
        const int qi = qbase + j;
        const float nx = -2.0f * q[qi * 3 + 0];
        const float ny = -2.0f * q[qi * 3 + 1];
        const float nz = -2.0f * q[qi * 3 + 2];
        cx2[j] = pack2(nx, nx);
        cy2[j] = pack2(ny, ny);
        cz2[j] = pack2(nz, nz);
        best[j] = FLT_MAX;
        bsub[j] = 0;
    }

    __shared__ ull sx[TP], sy[TP], sz[TP], sw[TP];   // 32 KB

    const int pbase = part * PART;

    // tile load: pack candidate pairs, precompute |p|^2 (fixed op order)
    for (int u = tid; u < TP; u += 256) {
        const float2* pp = (const float2*)(pos + (size_t)(pbase + 2 * u) * 3);
        const float2 a = pp[0];            // x0 y0
        const float2 b = pp[1];            // z0 x1
        const float2 c = pp[2];            // y1 z1
        const ull x2 = pack2(a.x, b.y);
        const ull y2 = pack2(a.y, c.x);
        const ull z2 = pack2(b.x, c.y);
        ull w2 = mul2(z2, z2);
        w2 = fma2(y2, y2, w2);
        w2 = fma2(x2, x2, w2);
        sx[u] = x2; sy[u] = y2; sz[u] = z2; sw[u] = w2;
    }
    __syncthreads();

#pragma unroll 1
    for (int s = 0; s < NSUB; s++) {
        float tmin[QPW];
#pragma unroll
        for (int j = 0; j < QPW; j++) tmin[j] = best[j];

#pragma unroll
        for (int kk = 0; kk < SUBP / 32; kk++) {       // 4 k-iters
            const int k = s * SUBP + kk * 32 + lane;
            const ull x2 = sx[k];
            const ull y2 = sy[k];
            const ull z2 = sz[k];
            const ull w2 = sw[k];
#pragma unroll
            for (int j = 0; j < QPW; j++) {
                ull t2 = fma2(x2, cx2[j], w2);
                t2 = fma2(y2, cy2[j], t2);
                float lo, hi;
                fma2u(z2, cz2[j], t2, lo, hi);
                tmin[j] = fminf(tmin[j], fminf(lo, hi));
            }
        }

        const int gb = pbase + s * (2 * SUBP);         // candidate base
#pragma unroll
        for (int j = 0; j < QPW; j++) {
            if (tmin[j] < best[j]) { best[j] = tmin[j]; bsub[j] = gb; }
        }
    }

    // cross-lane lexicographic (best, bsub) reduce
#pragma unroll
    for (int off = 16; off; off >>= 1) {
#pragma unroll
        for (int j = 0; j < QPW; j++) {
            const float ob = __shfl_xor_sync(0xffffffffu, best[j], off);
            const int   og = __shfl_xor_sync(0xffffffffu, bsub[j], off);
            if (ob < best[j] || (ob == best[j] && og < bsub[j])) {
                best[j] = ob; bsub[j] = og;
            }
        }
    }
    if (lane == 0) {
#pragma unroll
        for (int j = 0; j < QPW; j++)
            g_nn_part[search][qbase + j][part] =
                make_float2(best[j], __int_as_float(bsub[j]));
    }
}

// ---------------------------------------------------------------------------
// Kernel 2: resolve partitions + rescan 256-cand sub-block for exact index,
// then gather feat rows, avg left/right, max-pool (atomicMax, deterministic).
// Grid: 256 blocks = 2 sides x 128 chunks (16 rows). 256 thr. (R5-proven.)
// ---------------------------------------------------------------------------
__global__ __launch_bounds__(256)
void gather_kernel(const float* __restrict__ co, const float* __restrict__ cm,
                   const float* __restrict__ p0, const float* __restrict__ p1,
                   const float* __restrict__ p2, const float* __restrict__ p3,
                   const float* __restrict__ f0, const float* __restrict__ f1,
                   const float* __restrict__ f2, const float* __restrict__ f3)
{
    const int side  = blockIdx.x >> 7;     // 0 = orig, 1 = mut
    const int chunk = blockIdx.x & 127;
    const int m0    = chunk * 16;
    const int tid   = threadIdx.x;
    const int warp  = tid >> 5;
    const int lane  = tid & 31;

    __shared__ int sj[2][16];

    // 8 warps x 4 (which,row) pairs = 32 resolves+rescans, each done once.
    for (int pr = warp * 4; pr < warp * 4 + 4; pr++) {
        const int which = pr >> 4;                     // 0 = left, 1 = right
        const int ml    = pr & 15;
        const int m     = m0 + ml;
        const int s     = side * 2 + which;

        // resolve across 16 partitions: lex-min (d2, sub-base)
        float v;
        int   g;
        if (lane < NPART) {
            const float2 p = g_nn_part[s][m][lane];
            v = p.x; g = __float_as_int(p.y);
        } else {
            v = FLT_MAX; g = 0x7fffffff;
        }
#pragma unroll
        for (int off = 16; off; off >>= 1) {
            const float ov = __shfl_xor_sync(0xffffffffu, v, off);
            const int   og = __shfl_xor_sync(0xffffffffu, g, off);
            if (ov < v || (ov == v && og < g)) { v = ov; g = og; }
        }
        const float wbest = v;      // warp-uniform
        const int   gb    = g;      // winning 256-cand sub-block base (even)

        // query constants (identical math to nn_kernel)
        const float* __restrict__ qb = (s < 2) ? co : cm;
        const float nx = -2.0f * qb[m * 3 + 0];
        const float ny = -2.0f * qb[m * 3 + 1];
        const float nz = -2.0f * qb[m * 3 + 2];
        const ull cx2 = pack2(nx, nx);
        const ull cy2 = pack2(ny, ny);
        const ull cz2 = pack2(nz, nz);

        const float* __restrict__ pos = (s == 0) ? p0 : (s == 1) ? p1 :
                                        (s == 2) ? p2 : p3;

        int midx = 0x7fffffff;
#pragma unroll
        for (int kk = 0; kk < SUBP / 32; kk++) {       // 4 k-iters
            const int i0 = gb + 2 * (kk * 32 + lane);
            const float2* pp = (const float2*)(pos + (size_t)i0 * 3);
            const float2 a = pp[0];
            const float2 b = pp[1];
            const float2 c = pp[2];
            const ull x2 = pack2(a.x, b.y);
            const ull y2 = pack2(a.y, c.x);
            const ull z2 = pack2(b.x, c.y);
            ull w2 = mul2(z2, z2);
            w2 = fma2(y2, y2, w2);
            w2 = fma2(x2, x2, w2);
            ull t2 = fma2(x2, cx2, w2);
            t2 = fma2(y2, cy2, t2);
            float lo, hi;
            fma2u(z2, cz2, t2, lo, hi);
            if (lo == wbest) midx = min(midx, i0);
            if (hi == wbest) midx = min(midx, i0 + 1);
        }
#pragma unroll
        for (int off = 16; off; off >>= 1)
            midx = min(midx, __shfl_xor_sync(0xffffffffu, midx, off));

        if (lane == 0) sj[which][ml] = midx;
    }
    __syncthreads();

    const float* __restrict__ fa = side ? f2 : f0;
    const float* __restrict__ fb = side ? f3 : f1;
    const int c = tid;

    float mx = -FLT_MAX;
#pragma unroll
    for (int m = 0; m < 16; m++) {
        const float val = 0.5f * (fa[(size_t)sj[0][m] * D_F + c] +
                                  fb[(size_t)sj[1][m] * D_F + c]);
        mx = fmaxf(mx, val);
    }
    atomicMax(&g_xmax[side * 256 + c], enc_f(mx));
}

// ---------------------------------------------------------------------------
// Kernel 3: fc1 over 128 blocks (4 rows each, warp per row); last block
// finishes fc2 (threadfence-reduction pattern, deterministic order).
// ---------------------------------------------------------------------------
__global__ __launch_bounds__(128)
void fc_kernel(const float* __restrict__ w1, const float* __restrict__ b1,
               const float* __restrict__ w2, const float* __restrict__ b2,
               float* __restrict__ out)
{
    __shared__ float xs[D2];
    __shared__ bool  is_last;
    __shared__ float red[4];
    const int tid  = threadIdx.x;
    const int warp = tid >> 5;
    const int lane = tid & 31;

    for (int i = tid; i < D2; i += 128) xs[i] = dec_f(g_xmax[i]);
    __syncthreads();

    const int j = blockIdx.x * 4 + warp;
    const float4* __restrict__ wr4 = (const float4*)(w1 + (size_t)j * D2);
    const float4* __restrict__ xs4 = (const float4*)xs;

    float acc = 0.0f;
#pragma unroll
    for (int k = lane; k < D2 / 4; k += 32) {          // 4 float4 per lane
        const float4 w = wr4[k];
        const float4 x = xs4[k];
        acc = fmaf(w.x, x.x, acc);
        acc = fmaf(w.y, x.y, acc);
        acc = fmaf(w.z, x.z, acc);
        acc = fmaf(w.w, x.w, acc);
    }
#pragma unroll
    for (int off = 16; off; off >>= 1)
        acc += __shfl_down_sync(0xffffffffu, acc, off);

    if (lane == 0)
        g_h[j] = fmaxf(acc + b1[j], 0.0f) * w2[j];

    // last-block fc2
    __threadfence();
    __syncthreads();
    if (tid == 0)
        is_last = (atomicAdd(&g_tick, 1u) == 127u);
    __syncthreads();

    if (is_last) {
        __threadfence();                    // acquire all g_h writes
        const float4 v = ((const float4*)g_h)[tid];     // 128 x float4 = 512
        float a2 = v.x + v.y + v.z + v.w;
#pragma unroll
        for (int off = 16; off; off >>= 1)
            a2 += __shfl_down_sync(0xffffffffu, a2, off);
        if (lane == 0) red[warp] = a2;
        __syncthreads();
        if (tid == 0)
            out[0] = red[0] + red[1] + red[2] + red[3] + b2[0];
    }
}

// ---------------------------------------------------------------------------
// Launch
// ---------------------------------------------------------------------------
extern "C" void kernel_launch(void* const* d_in, const int* in_sizes, int n_in,
                              void* d_out, int out_size)
{
    const float* co = (const float*)d_in[0];
    const float* cm = (const float*)d_in[1];
    const float* p0 = (const float*)d_in[2];
    const float* p1 = (const float*)d_in[3];
    const float* p2 = (const float*)d_in[4];
    const float* p3 = (const float*)d_in[5];
    const float* f0 = (const float*)d_in[6];
    const float* f1 = (const float*)d_in[7];
    const float* f2 = (const float*)d_in[8];
    const float* f3 = (const float*)d_in[9];
    const float* w1 = (const float*)d_in[10];
    const float* b1 = (const float*)d_in[11];
    const float* w2 = (const float*)d_in[12];
    const float* b2 = (const float*)d_in[13];
    float* out = (float*)d_out;

    nn_kernel<<<2048, 256>>>(co, cm, p0, p1, p2, p3);
    gather_kernel<<<256, 256>>>(co, cm, p0, p1, p2, p3, f0, f1, f2, f3);
    fc_kernel<<<128, 128>>>(w1, b1, w2, b2, out);
}

// round 9
// speedup vs baseline: 1.6670x; 1.0068x over previous
#include <cuda_runtime.h>
#include <float.h>

// ---------------------------------------------------------------------------
// Problem shape
// ---------------------------------------------------------------------------
#define M_Q   2048
#define N_P   32768
#define D_F   256
#define D2    512

#define NPART 16
#define PART  (N_P / NPART)      // 2048 candidates per partition (== one tile)
#define TP    (PART / 2)         // 1024 packed units
#define QPW   8                  // queries per warp
#define SUBP  256                // packed units per sub-block (512 candidates)
#define NSUB  (TP / SUBP)        // 4 sub-blocks

typedef unsigned long long ull;

// ---------------------------------------------------------------------------
// Device scratch
// ---------------------------------------------------------------------------
__device__ float2       g_nn_part[4][M_Q][NPART];  // (best d2', sub-base bits)
__device__ unsigned int g_xmax[D2];                // order-encoded channel max
__device__ float        g_h[D2];                   // fc1 out * w2
__device__ unsigned int g_tick;                    // fc last-block ticket

// ---------------------------------------------------------------------------
// Packed f32x2 helpers
// ---------------------------------------------------------------------------
__device__ __forceinline__ ull fma2(ull a, ull b, ull c) {
    ull d;
    asm("fma.rn.f32x2 %0, %1, %2, %3;" : "=l"(d) : "l"(a), "l"(b), "l"(c));
    return d;
}
__device__ __forceinline__ ull mul2(ull a, ull b) {
    ull d;
    asm("mul.rn.f32x2 %0, %1, %2;" : "=l"(d) : "l"(a), "l"(b));
    return d;
}
__device__ __forceinline__ void fma2u(ull a, ull b, ull c, float& lo, float& hi) {
    asm("{\n\t.reg .b64 t;\n\t"
        "fma.rn.f32x2 t, %2, %3, %4;\n\t"
        "mov.b64 {%0, %1}, t;\n\t}"
        : "=f"(lo), "=f"(hi) : "l"(a), "l"(b), "l"(c));
}
__device__ __forceinline__ ull pack2(float lo, float hi) {
    ull r;
    asm("mov.b64 %0, {%1, %2};" : "=l"(r) : "f"(lo), "f"(hi));
    return r;
}

// Order-preserving float<->uint for atomicMax over mixed-sign floats.
__device__ __forceinline__ unsigned int enc_f(float f) {
    unsigned int u = __float_as_uint(f);
    return (u & 0x80000000u) ? ~u : (u | 0x80000000u);
}
__device__ __forceinline__ float dec_f(unsigned int u) {
    return __uint_as_float((u & 0x80000000u) ? (u & 0x7FFFFFFFu) : ~u);
}

// ---------------------------------------------------------------------------
// Kernel 1: brute-force NN, min-only loop + 512-cand sub-block tracking.
// d2' = |p|^2 - 2 q.p  (argmin-equivalent to |q-p|^2)
// Grid: 2048 blocks = 32 qblocks x 4 searches x 16 partitions. 256 thr.
// (R7-proven inner loop; SUBP doubled to 256.)
// ---------------------------------------------------------------------------
__global__ __launch_bounds__(256, 3)
void nn_kernel(const float* __restrict__ co, const float* __restrict__ cm,
               const float* __restrict__ p0, const float* __restrict__ p1,
               const float* __restrict__ p2, const float* __restrict__ p3)
{
    const int bx     = blockIdx.x;
    const int part   = bx & 15;
    const int search = (bx >> 4) & 3;
    const int qblk   = bx >> 6;               // 0..31
    const int tid    = threadIdx.x;
    const int warp   = tid >> 5;
    const int lane   = tid & 31;

    if (bx < 2) g_xmax[bx * 256 + tid] = 0u;  // init for gather stage
    if (bx == 0 && tid == 0) g_tick = 0u;     // init fc ticket

    const float* __restrict__ q   = (search < 2) ? co : cm;
    const float* __restrict__ pos = (search == 0) ? p0 :
                                    (search == 1) ? p1 :
                                    (search == 2) ? p2 : p3;

    const int qbase = qblk * 64 + warp * QPW;

    ull   cx2[QPW], cy2[QPW], cz2[QPW];
    float best[QPW];
    int   bsub[QPW];
#pragma unroll
    for (int j = 0; j < QPW; j++) {
        const int qi = qbase + j;
        const float nx = -2.0f * q[qi * 3 + 0];
        const float ny = -2.0f * q[qi * 3 + 1];
        const float nz = -2.0f * q[qi * 3 + 2];
        cx2[j] = pack2(nx, nx);
        cy2[j] = pack2(ny, ny);
        cz2[j] = pack2(nz, nz);
        best[j] = FLT_MAX;
        bsub[j] = 0;
    }

    __shared__ ull sx[TP], sy[TP], sz[TP], sw[TP];   // 32 KB

    const int pbase = part * PART;

    // tile load: pack candidate pairs, precompute |p|^2 (fixed op order)
    for (int u = tid; u < TP; u += 256) {
        const float2* pp = (const float2*)(pos + (size_t)(pbase + 2 * u) * 3);
        const float2 a = pp[0];            // x0 y0
        const float2 b = pp[1];            // z0 x1
        const float2 c = pp[2];            // y1 z1
        const ull x2 = pack2(a.x, b.y);
        const ull y2 = pack2(a.y, c.x);
        const ull z2 = pack2(b.x, c.y);
        ull w2 = mul2(z2, z2);
        w2 = fma2(y2, y2, w2);
        w2 = fma2(x2, x2, w2);
        sx[u] = x2; sy[u] = y2; sz[u] = z2; sw[u] = w2;
    }
    __syncthreads();

#pragma unroll 1
    for (int s = 0; s < NSUB; s++) {
        float tmin[QPW];
#pragma unroll
        for (int j = 0; j < QPW; j++) tmin[j] = best[j];

#pragma unroll
        for (int kk = 0; kk < SUBP / 32; kk++) {       // 8 k-iters
            const int k = s * SUBP + kk * 32 + lane;
            const ull x2 = sx[k];
            const ull y2 = sy[k];
            const ull z2 = sz[k];
            const ull w2 = sw[k];
#pragma unroll
            for (int j = 0; j < QPW; j++) {
                ull t2 = fma2(x2, cx2[j], w2);
                t2 = fma2(y2, cy2[j], t2);
                float lo, hi;
                fma2u(z2, cz2[j], t2, lo, hi);
                tmin[j] = fminf(tmin[j], fminf(lo, hi));
            }
        }

        const int gb = pbase + s * (2 * SUBP);         // candidate base
#pragma unroll
        for (int j = 0; j < QPW; j++) {
            if (tmin[j] < best[j]) { best[j] = tmin[j]; bsub[j] = gb; }
        }
    }

    // cross-lane lexicographic (best, bsub) reduce
#pragma unroll
    for (int off = 16; off; off >>= 1) {
#pragma unroll
        for (int j = 0; j < QPW; j++) {
            const float ob = __shfl_xor_sync(0xffffffffu, best[j], off);
            const int   og = __shfl_xor_sync(0xffffffffu, bsub[j], off);
            if (ob < best[j] || (ob == best[j] && og < bsub[j])) {
                best[j] = ob; bsub[j] = og;
            }
        }
    }
    if (lane == 0) {
#pragma unroll
        for (int j = 0; j < QPW; j++)
            g_nn_part[search][qbase + j][part] =
                make_float2(best[j], __int_as_float(bsub[j]));
    }
}

// ---------------------------------------------------------------------------
// Kernel 2: resolve partitions + rescan 512-cand sub-block for exact index,
// then gather feat rows, avg left/right, max-pool (atomicMax, deterministic).
// Grid: 512 blocks = 2 sides x 256 chunks (8 rows each). 256 thr.
// ---------------------------------------------------------------------------
__global__ __launch_bounds__(256)
void gather_kernel(const float* __restrict__ co, const float* __restrict__ cm,
                   const float* __restrict__ p0, const float* __restrict__ p1,
                   const float* __restrict__ p2, const float* __restrict__ p3,
                   const float* __restrict__ f0, const float* __restrict__ f1,
                   const float* __restrict__ f2, const float* __restrict__ f3)
{
    const int side  = blockIdx.x >> 8;     // 0 = orig, 1 = mut
    const int chunk = blockIdx.x & 255;
    const int m0    = chunk * 8;
    const int tid   = threadIdx.x;
    const int warp  = tid >> 5;
    const int lane  = tid & 31;

    __shared__ int sj[2][8];

    // 8 warps x 2 (which,row) pairs = 16 resolves+rescans, each done once.
    for (int pr = warp * 2; pr < warp * 2 + 2; pr++) {
        const int which = pr >> 3;                     // 0 = left, 1 = right
        const int ml    = pr & 7;
        const int m     = m0 + ml;
        const int s     = side * 2 + which;

        // resolve across 16 partitions: lex-min (d2, sub-base)
        float v;
        int   g;
        if (lane < NPART) {
            const float2 p = g_nn_part[s][m][lane];
            v = p.x; g = __float_as_int(p.y);
        } else {
            v = FLT_MAX; g = 0x7fffffff;
        }
#pragma unroll
        for (int off = 16; off; off >>= 1) {
            const float ov = __shfl_xor_sync(0xffffffffu, v, off);
            const int   og = __shfl_xor_sync(0xffffffffu, g, off);
            if (ov < v || (ov == v && og < g)) { v = ov; g = og; }
        }
        const float wbest = v;      // warp-uniform
        const int   gb    = g;      // winning 512-cand sub-block base (even)

        // query constants (identical math to nn_kernel)
        const float* __restrict__ qb = (s < 2) ? co : cm;
        const float nx = -2.0f * qb[m * 3 + 0];
        const float ny = -2.0f * qb[m * 3 + 1];
        const float nz = -2.0f * qb[m * 3 + 2];
        const ull cx2 = pack2(nx, nx);
        const ull cy2 = pack2(ny, ny);
        const ull cz2 = pack2(nz, nz);

        const float* __restrict__ pos = (s == 0) ? p0 : (s == 1) ? p1 :
                                        (s == 2) ? p2 : p3;

        int midx = 0x7fffffff;
#pragma unroll
        for (int kk = 0; kk < SUBP / 32; kk++) {       // 8 k-iters, 512 cands
            const int i0 = gb + 2 * (kk * 32 + lane);
            const float2* pp = (const float2*)(pos + (size_t)i0 * 3);
            const float2 a = pp[0];
            const float2 b = pp[1];
            const float2 c = pp[2];
            const ull x2 = pack2(a.x, b.y);
            const ull y2 = pack2(a.y, c.x);
            const ull z2 = pack2(b.x, c.y);
            ull w2 = mul2(z2, z2);
            w2 = fma2(y2, y2, w2);
            w2 = fma2(x2, x2, w2);
            ull t2 = fma2(x2, cx2, w2);
            t2 = fma2(y2, cy2, t2);
            float lo, hi;
            fma2u(z2, cz2, t2, lo, hi);
            if (lo == wbest) midx = min(midx, i0);
            if (hi == wbest) midx = min(midx, i0 + 1);
        }
#pragma unroll
        for (int off = 16; off; off >>= 1)
            midx = min(midx, __shfl_xor_sync(0xffffffffu, midx, off));

        if (lane == 0) sj[which][ml] = midx;
    }
    __syncthreads();

    const float* __restrict__ fa = side ? f2 : f0;
    const float* __restrict__ fb = side ? f3 : f1;
    const int c = tid;

    float mx = -FLT_MAX;
#pragma unroll
    for (int m = 0; m < 8; m++) {
        const float val = 0.5f * (fa[(size_t)sj[0][m] * D_F + c] +
                                  fb[(size_t)sj[1][m] * D_F + c]);
        mx = fmaxf(mx, val);
    }
    atomicMax(&g_xmax[side * 256 + c], enc_f(mx));
}

// ---------------------------------------------------------------------------
// Kernel 3: fc1 over 128 blocks (4 rows each, warp per row); last block
// finishes fc2 (threadfence-reduction pattern, deterministic order).
// ---------------------------------------------------------------------------
__global__ __launch_bounds__(128)
void fc_kernel(const float* __restrict__ w1, const float* __restrict__ b1,
               const float* __restrict__ w2, const float* __restrict__ b2,
               float* __restrict__ out)
{
    __shared__ float xs[D2];
    __shared__ bool  is_last;
    __shared__ float red[4];
    const int tid  = threadIdx.x;
    const int warp = tid >> 5;
    const int lane = tid & 31;

    for (int i = tid; i < D2; i += 128) xs[i] = dec_f(g_xmax[i]);
    __syncthreads();

    const int j = blockIdx.x * 4 + warp;
    const float4* __restrict__ wr4 = (const float4*)(w1 + (size_t)j * D2);
    const float4* __restrict__ xs4 = (const float4*)xs;

    float acc = 0.0f;
#pragma unroll
    for (int k = lane; k < D2 / 4; k += 32) {          // 4 float4 per lane
        const float4 w = wr4[k];
        const float4 x = xs4[k];
        acc = fmaf(w.x, x.x, acc);
        acc = fmaf(w.y, x.y, acc);
        acc = fmaf(w.z, x.z, acc);
        acc = fmaf(w.w, x.w, acc);
    }
#pragma unroll
    for (int off = 16; off; off >>= 1)
        acc += __shfl_down_sync(0xffffffffu, acc, off);

    if (lane == 0)
        g_h[j] = fmaxf(acc + b1[j], 0.0f) * w2[j];

    // last-block fc2
    __threadfence();
    __syncthreads();
    if (tid == 0)
        is_last = (atomicAdd(&g_tick, 1u) == 127u);
    __syncthreads();

    if (is_last) {
        __threadfence();                    // acquire all g_h writes
        const float4 v = ((const float4*)g_h)[tid];     // 128 x float4 = 512
        float a2 = v.x + v.y + v.z + v.w;
#pragma unroll
        for (int off = 16; off; off >>= 1)
            a2 += __shfl_down_sync(0xffffffffu, a2, off);
        if (lane == 0) red[warp] = a2;
        __syncthreads();
        if (tid == 0)
            out[0] = red[0] + red[1] + red[2] + red[3] + b2[0];
    }
}

// ---------------------------------------------------------------------------
// Launch
// ---------------------------------------------------------------------------
extern "C" void kernel_launch(void* const* d_in, const int* in_sizes, int n_in,
                              void* d_out, int out_size)
{
    const float* co = (const float*)d_in[0];
    const float* cm = (const float*)d_in[1];
    const float* p0 = (const float*)d_in[2];
    const float* p1 = (const float*)d_in[3];
    const float* p2 = (const float*)d_in[4];
    const float* p3 = (const float*)d_in[5];
    const float* f0 = (const float*)d_in[6];
    const float* f1 = (const float*)d_in[7];
    const float* f2 = (const float*)d_in[8];
    const float* f3 = (const float*)d_in[9];
    const float* w1 = (const float*)d_in[10];
    const float* b1 = (const float*)d_in[11];
    const float* w2 = (const float*)d_in[12];
    const float* b2 = (const float*)d_in[13];
    float* out = (float*)d_out;

    nn_kernel<<<2048, 256>>>(co, cm, p0, p1, p2, p3);
    gather_kernel<<<512, 256>>>(co, cm, p0, p1, p2, p3, f0, f1, f2, f3);
    fc_kernel<<<128, 128>>>(w1, b1, w2, b2, out);
}